// round 5
// baseline (speedup 1.0000x reference)
#include <cuda_runtime.h>

#define Nn    50000
#define Ee    800000
#define Ff    4
#define Tt    12
#define Cc    32
#define HORZ  12
#define FT    (Ff*Tt)     // 48
#define TILE  512
#define NTILES ((Nn + TILE - 1) / TILE)   // 98

// ---------------- scratch (device globals; no allocation allowed) ----------
__device__ float  g_deg[Nn];
__device__ float  g_dis[Nn];
__device__ int    g_cnt[Nn];          // per-node in-degree (edge count)
__device__ int    g_ptr[Nn + 1];      // CSR row pointers (by col)
__device__ int    g_cur[Nn];          // scatter cursors
__device__ int    g_tilesum[NTILES];
__device__ int    g_tileoff[NTILES];
__device__ int    g_srow[Ee];         // CSR-sorted source row
__device__ float  g_snorm[Ee];        // CSR-sorted edge norm
__device__ float  g_Xagg[Nn * FT];    // aggregated features [n][48]
__device__ float  g_Mz[Ff*Cc];        // Wz @ Wlz[:C]
__device__ float  g_Mh[Ff*Cc];        // Wh @ Wlh[:C]
__device__ float  g_cz[Cc];           // bz @ Wlz[:C] + blz
__device__ float  g_ch[Cc];
__device__ float  g_probs[Tt];

// ---------------- tiny setup: folded weights + softmax ---------------------
__global__ void k_setup(const float* __restrict__ att,
                        const float* __restrict__ Wz, const float* __restrict__ bz,
                        const float* __restrict__ Wlz, const float* __restrict__ blz,
                        const float* __restrict__ Wh, const float* __restrict__ bh,
                        const float* __restrict__ Wlh, const float* __restrict__ blh) {
    int tid = threadIdx.x;
    if (tid < Ff*Cc) {
        int f = tid / Cc, c = tid % Cc;
        float sz = 0.f, sh = 0.f;
        #pragma unroll
        for (int k = 0; k < Cc; ++k) {
            sz += Wz[f*Cc + k] * Wlz[k*Cc + c];   // Wlz rows 0..C-1 only (H0 == 0)
            sh += Wh[f*Cc + k] * Wlh[k*Cc + c];
        }
        g_Mz[tid] = sz;
        g_Mh[tid] = sh;
    }
    if (tid < Cc) {
        float sz = 0.f, sh = 0.f;
        #pragma unroll
        for (int k = 0; k < Cc; ++k) {
            sz += bz[k] * Wlz[k*Cc + tid];
            sh += bh[k] * Wlh[k*Cc + tid];
        }
        g_cz[tid] = sz + blz[tid];
        g_ch[tid] = sh + blh[tid];
    }
    if (tid == 0) {
        float m = -1e30f;
        for (int t = 0; t < Tt; ++t) m = fmaxf(m, att[t]);
        float e[Tt], s = 0.f;
        for (int t = 0; t < Tt; ++t) { e[t] = expf(att[t] - m); s += e[t]; }
        float inv = 1.f / s;
        for (int t = 0; t < Tt; ++t) g_probs[t] = e[t] * inv;
    }
}

// ---------------- zero degree + histogram ----------------------------------
__global__ void k_zero() {
    int i = blockIdx.x * blockDim.x + threadIdx.x;
    if (i < Nn) { g_deg[i] = 0.f; g_cnt[i] = 0; }
}

// edge_index is INT32 (JAX x64 disabled downcasts the declared int64)
__global__ void k_deg_hist(const int* __restrict__ ei,
                           const float* __restrict__ ew) {
    int e = blockIdx.x * blockDim.x + threadIdx.x;
    if (e >= Ee) return;
    int col = ei[Ee + e];
    atomicAdd(&g_deg[col], ew[e]);
    atomicAdd(&g_cnt[col], 1);
}

__global__ void k_dis() {
    int i = blockIdx.x * blockDim.x + threadIdx.x;
    if (i < Nn) g_dis[i] = rsqrtf(g_deg[i] + 1.f);
}

// ---------------- two-level exclusive scan of g_cnt -> g_ptr ---------------
// pass 1: per-tile local exclusive scan (into g_ptr) + tile totals
__global__ void k_localscan() {
    __shared__ int sh[TILE];
    int t = threadIdx.x;
    int i = blockIdx.x * TILE + t;
    int v = (i < Nn) ? g_cnt[i] : 0;
    sh[t] = v;
    __syncthreads();
    #pragma unroll
    for (int off = 1; off < TILE; off <<= 1) {
        int add = (t >= off) ? sh[t - off] : 0;
        __syncthreads();
        sh[t] += add;
        __syncthreads();
    }
    if (i < Nn) g_ptr[i] = sh[t] - v;          // local exclusive
    if (t == TILE - 1) g_tilesum[blockIdx.x] = sh[t];
}

// pass 2: scan tile totals (single block, 128 threads)
__global__ void k_tilescan() {
    int t = threadIdx.x;  // 128 >= NTILES
    int v = (t < NTILES) ? g_tilesum[t] : 0;
    int incl = v;
    #pragma unroll
    for (int off = 1; off < 32; off <<= 1) {
        int u = __shfl_up_sync(0xffffffffu, incl, off);
        if ((t & 31) >= off) incl += u;
    }
    __shared__ int wtot[4];
    if ((t & 31) == 31) wtot[t >> 5] = incl;
    __syncthreads();
    int woff = 0;
    for (int w = 0; w < (t >> 5); ++w) woff += wtot[w];
    if (t < NTILES) g_tileoff[t] = woff + incl - v;
    if (t == 0) g_ptr[Nn] = Ee;
}

// pass 3: add tile offsets, init cursors
__global__ void k_addoff() {
    int i = blockIdx.x * blockDim.x + threadIdx.x;
    if (i >= Nn) return;
    int p = g_ptr[i] + g_tileoff[i / TILE];
    g_ptr[i] = p;
    g_cur[i] = p;
}

// ---------------- scatter edges into CSR slots -----------------------------
__global__ void k_scatter(const int* __restrict__ ei,
                          const float* __restrict__ ew) {
    int e = blockIdx.x * blockDim.x + threadIdx.x;
    if (e >= Ee) return;
    int r = ei[e];
    int c = ei[Ee + e];
    float nm = g_dis[r] * ew[e] * g_dis[c];
    int pos = atomicAdd(&g_cur[c], 1);
    g_srow[pos]  = r;
    g_snorm[pos] = nm;
}

// ---------------- gather aggregation: one warp per node, no float atomics --
__global__ void k_agg(const float* __restrict__ x) {
    int warp = (blockIdx.x * blockDim.x + threadIdx.x) >> 5;
    int lane = threadIdx.x & 31;
    if (warp >= Nn) return;

    int beg = g_ptr[warp];
    int end = g_ptr[warp + 1];
    float d  = g_dis[warp];
    float sn = d * d;

    const float2* __restrict__ X2 = (const float2*)x;   // [n][24] float2
    bool active = lane < (FT / 2);                      // 24 active lanes
    float2 acc = make_float2(0.f, 0.f);
    if (active) {                                       // self-loop term
        float2 v = X2[warp * (FT/2) + lane];
        acc.x = sn * v.x;
        acc.y = sn * v.y;
    }

    for (int base = beg; base < end; base += 32) {
        int k = base + lane;
        int   r  = 0;
        float nm = 0.f;
        if (k < end) { r = g_srow[k]; nm = g_snorm[k]; }
        int cnt = min(32, end - base);
        for (int i = 0; i < cnt; ++i) {
            int   rr = __shfl_sync(0xffffffffu, r,  i);
            float nn = __shfl_sync(0xffffffffu, nm, i);
            if (active) {
                float2 v = X2[rr * (FT/2) + lane];
                acc.x += nn * v.x;
                acc.y += nn * v.y;
            }
        }
    }
    if (active)
        ((float2*)g_Xagg)[warp * (FT/2) + lane] = acc;
}

// ---------------- per-node GRU-lite epilogue (one warp per node) -----------
__global__ void k_final(const float* __restrict__ Wout,
                        const float* __restrict__ bout,
                        float* __restrict__ out) {
    int warp = (blockIdx.x * blockDim.x + threadIdx.x) >> 5;
    int lane = threadIdx.x & 31;
    if (warp >= Nn) return;

    const float* xa = g_Xagg + warp * FT;

    float mz0 = g_Mz[lane],        mz1 = g_Mz[Cc + lane];
    float mz2 = g_Mz[2*Cc + lane], mz3 = g_Mz[3*Cc + lane];
    float mh0 = g_Mh[lane],        mh1 = g_Mh[Cc + lane];
    float mh2 = g_Mh[2*Cc + lane], mh3 = g_Mh[3*Cc + lane];
    float cz  = g_cz[lane],        ch  = g_ch[lane];

    float Hacc = 0.f;
    #pragma unroll
    for (int t = 0; t < Tt; ++t) {
        float a0 = xa[t], a1 = xa[Tt + t], a2 = xa[2*Tt + t], a3 = xa[3*Tt + t];
        float zp = cz + a0*mz0 + a1*mz1 + a2*mz2 + a3*mz3;
        float hp = ch + a0*mh0 + a1*mh1 + a2*mh2 + a3*mh3;
        float Z  = 1.f / (1.f + __expf(-zp));
        float Ht = tanhf(hp);
        Hacc += g_probs[t] * (1.f - Z) * Ht;   // Hn = Z*0 + (1-Z)*Ht
    }
    float h = fmaxf(Hacc, 0.f);

    float o[HORZ];
    #pragma unroll
    for (int j = 0; j < HORZ; ++j) o[j] = h * Wout[lane*HORZ + j];
    #pragma unroll
    for (int off = 16; off; off >>= 1)
        #pragma unroll
        for (int j = 0; j < HORZ; ++j)
            o[j] += __shfl_xor_sync(0xffffffffu, o[j], off);

    if (lane == 0) {
        #pragma unroll
        for (int j = 0; j < HORZ; ++j)
            out[warp*HORZ + j] = o[j] + bout[j];
    }
}

// ---------------- launch ----------------------------------------------------
extern "C" void kernel_launch(void* const* d_in, const int* in_sizes, int n_in,
                              void* d_out, int out_size) {
    const float* x    = (const float*)d_in[0];
    const int*   ei   = (const int*)d_in[1];     // int32! (JAX x64 disabled)
    const float* ew   = (const float*)d_in[2];
    const float* att  = (const float*)d_in[3];
    const float* Wz   = (const float*)d_in[4];
    const float* bz   = (const float*)d_in[5];
    const float* Wlz  = (const float*)d_in[6];
    const float* blz  = (const float*)d_in[7];
    // d_in[8..11] = Wr, br, Wlr, blr  -> dead (H0 == 0 forever)
    const float* Wh   = (const float*)d_in[12];
    const float* bh   = (const float*)d_in[13];
    const float* Wlh  = (const float*)d_in[14];
    const float* blh  = (const float*)d_in[15];
    const float* Wout = (const float*)d_in[16];
    const float* bout = (const float*)d_in[17];
    float*       out  = (float*)d_out;

    k_setup<<<1, 128>>>(att, Wz, bz, Wlz, blz, Wh, bh, Wlh, blh);
    k_zero<<<(Nn + 255) / 256, 256>>>();
    k_deg_hist<<<(Ee + 255) / 256, 256>>>(ei, ew);
    k_dis<<<(Nn + 255) / 256, 256>>>();
    k_localscan<<<NTILES, TILE>>>();
    k_tilescan<<<1, 128>>>();
    k_addoff<<<(Nn + 255) / 256, 256>>>();
    k_scatter<<<(Ee + 255) / 256, 256>>>(ei, ew);
    k_agg<<<(Nn * 32 + 255) / 256, 256>>>(x);
    k_final<<<(Nn * 32 + 255) / 256, 256>>>(Wout, bout, out);
}

// round 6
// speedup vs baseline: 1.2458x; 1.2458x over previous
#include <cuda_runtime.h>

#define Nn    50000
#define Ee    800000
#define Ff    4
#define Tt    12
#define Cc    32
#define HORZ  12
#define FT    (Ff*Tt)     // 48
#define TILE  512
#define NTILES ((Nn + TILE - 1) / TILE)   // 98

// ---------------- scratch (device globals; no allocation allowed) ----------
// zeroed each run by one cudaMemsetAsync:
//   [0, Nn)       : weighted degree (float)
//   [Nn, 2Nn)     : edge count (int)
//   [2Nn]         : done-counter for last-block scan
__device__ unsigned int g_zero[2*Nn + 1];
__device__ float  g_dis[Nn];
__device__ int    g_ptrloc[Nn];       // tile-local exclusive scan of counts
__device__ int    g_cur[Nn];          // scatter cursors (tile-local)
__device__ int    g_tilesum[NTILES];
__device__ int    g_tileoff[NTILES];  // exclusive scan of tile sums
__device__ int2   g_edge[Ee];         // packed CSR payload {row, norm bits}
__device__ float  g_Mz[Ff*Cc];        // Wz @ Wlz[:C]
__device__ float  g_Mh[Ff*Cc];        // Wh @ Wlh[:C]
__device__ float  g_cz[Cc];           // bz @ Wlz[:C] + blz
__device__ float  g_ch[Cc];
__device__ float  g_probs[Tt];

// ---------------- histogram + (block 0) folded-weight setup ---------------
__global__ void k_hist(const int* __restrict__ ei, const float* __restrict__ ew,
                       const float* __restrict__ att,
                       const float* __restrict__ Wz, const float* __restrict__ bz,
                       const float* __restrict__ Wlz, const float* __restrict__ blz,
                       const float* __restrict__ Wh, const float* __restrict__ bh,
                       const float* __restrict__ Wlh, const float* __restrict__ blh) {
    float* deg = (float*)g_zero;
    int*   cnt = (int*)(g_zero + Nn);
    int e = blockIdx.x * blockDim.x + threadIdx.x;
    if (e < Ee) {
        int col = ei[Ee + e];
        atomicAdd(&deg[col], ew[e]);
        atomicAdd(&cnt[col], 1);
    }
    // block 0 additionally folds the weights (H0 == 0 forever -> R gate dead,
    // concat collapses: M = W @ Wl[:C], c = b @ Wl[:C] + bl)
    if (blockIdx.x == 0) {
        int tid = threadIdx.x;
        if (tid < Ff*Cc) {
            int f = tid / Cc, c = tid % Cc;
            float sz = 0.f, sh = 0.f;
            #pragma unroll
            for (int k = 0; k < Cc; ++k) {
                sz += Wz[f*Cc + k] * Wlz[k*Cc + c];
                sh += Wh[f*Cc + k] * Wlh[k*Cc + c];
            }
            g_Mz[tid] = sz;
            g_Mh[tid] = sh;
        }
        if (tid < Cc) {
            float sz = 0.f, sh = 0.f;
            #pragma unroll
            for (int k = 0; k < Cc; ++k) {
                sz += bz[k] * Wlz[k*Cc + tid];
                sh += bh[k] * Wlh[k*Cc + tid];
            }
            g_cz[tid] = sz + blz[tid];
            g_ch[tid] = sh + blh[tid];
        }
        if (tid == 0) {
            float m = -1e30f;
            for (int t = 0; t < Tt; ++t) m = fmaxf(m, att[t]);
            float ex[Tt], s = 0.f;
            for (int t = 0; t < Tt; ++t) { ex[t] = expf(att[t] - m); s += ex[t]; }
            float inv = 1.f / s;
            for (int t = 0; t < Tt; ++t) g_probs[t] = ex[t] * inv;
        }
    }
}

// ---------------- dis + per-tile scan + last-block tile-total scan ---------
__global__ void k_scan() {
    const float* deg = (const float*)g_zero;
    const int*   cnt = (const int*)(g_zero + Nn);
    __shared__ int sh[TILE];
    int t = threadIdx.x;
    int i = blockIdx.x * TILE + t;
    int v = (i < Nn) ? cnt[i] : 0;
    if (i < Nn) g_dis[i] = rsqrtf(deg[i] + 1.f);
    sh[t] = v;
    __syncthreads();
    #pragma unroll
    for (int off = 1; off < TILE; off <<= 1) {
        int add = (t >= off) ? sh[t - off] : 0;
        __syncthreads();
        sh[t] += add;
        __syncthreads();
    }
    if (i < Nn) { int p = sh[t] - v; g_ptrloc[i] = p; g_cur[i] = p; }
    if (t == TILE - 1) g_tilesum[blockIdx.x] = sh[t];

    // last-arriving block scans the 98 tile sums -> g_tileoff
    __threadfence();
    __shared__ int isLast;
    if (t == 0) {
        unsigned int old = atomicAdd(&g_zero[2*Nn], 1u);
        isLast = (old == NTILES - 1);
    }
    __syncthreads();
    if (isLast) {
        __shared__ int s2[128];
        int w = (t < NTILES) ? g_tilesum[t] : 0;
        if (t < 128) s2[t] = w;
        __syncthreads();
        #pragma unroll
        for (int off = 1; off < 128; off <<= 1) {
            int add = (t < 128 && t >= off) ? s2[t - off] : 0;
            __syncthreads();
            if (t < 128) s2[t] += add;
            __syncthreads();
        }
        if (t < NTILES) g_tileoff[t] = s2[t] - w;   // exclusive
    }
}

// ---------------- scatter edges into CSR slots (packed int2) ---------------
__global__ void k_scatter(const int* __restrict__ ei,
                          const float* __restrict__ ew) {
    int e = blockIdx.x * blockDim.x + threadIdx.x;
    if (e >= Ee) return;
    int r = ei[e];
    int c = ei[Ee + e];
    float nm = g_dis[r] * ew[e] * g_dis[c];
    int pos = atomicAdd(&g_cur[c], 1) + g_tileoff[c >> 9];
    g_edge[pos] = make_int2(r, __float_as_int(nm));
}

// ---------------- fused gather aggregation + GRU-lite epilogue -------------
// one warp per node; 48-vector transposed through 48B of shared per warp
__global__ void k_aggfinal(const float* __restrict__ x,
                           const float* __restrict__ Wout,
                           const float* __restrict__ bout,
                           float* __restrict__ out) {
    __shared__ float sh[8][FT];   // 8 warps/block
    int warp = (blockIdx.x * blockDim.x + threadIdx.x) >> 5;
    int wl   = threadIdx.x >> 5;
    int lane = threadIdx.x & 31;
    if (warp >= Nn) return;

    int beg = g_ptrloc[warp] + g_tileoff[warp >> 9];
    int end = (warp == Nn - 1) ? Ee
            : (g_ptrloc[warp + 1] + g_tileoff[(warp + 1) >> 9]);
    float d  = g_dis[warp];
    float sn = d * d;

    const float2* __restrict__ X2 = (const float2*)x;   // [n][24] float2
    bool active = lane < (FT/2);                        // 24 active lanes
    float2 acc = make_float2(0.f, 0.f);
    if (active) {                                       // self-loop term
        float2 v = X2[warp * (FT/2) + lane];
        acc.x = sn * v.x;
        acc.y = sn * v.y;
    }

    for (int base = beg; base < end; base += 32) {
        int k = base + lane;
        int2 ed = make_int2(0, 0);
        if (k < end) ed = g_edge[k];
        int cntv = min(32, end - base);
        for (int i = 0; i < cntv; ++i) {
            int   rr = __shfl_sync(0xffffffffu, ed.x, i);
            float nn = __int_as_float(__shfl_sync(0xffffffffu, ed.y, i));
            if (active) {
                float2 v = X2[rr * (FT/2) + lane];
                acc.x += nn * v.x;
                acc.y += nn * v.y;
            }
        }
    }
    if (active) {
        sh[wl][2*lane]     = acc.x;
        sh[wl][2*lane + 1] = acc.y;
    }
    __syncwarp();

    // ----- epilogue: lane = channel -----
    const float* xa = sh[wl];
    float mz0 = g_Mz[lane],        mz1 = g_Mz[Cc + lane];
    float mz2 = g_Mz[2*Cc + lane], mz3 = g_Mz[3*Cc + lane];
    float mh0 = g_Mh[lane],        mh1 = g_Mh[Cc + lane];
    float mh2 = g_Mh[2*Cc + lane], mh3 = g_Mh[3*Cc + lane];
    float cz  = g_cz[lane],        ch  = g_ch[lane];

    float Hacc = 0.f;
    #pragma unroll
    for (int t = 0; t < Tt; ++t) {
        float a0 = xa[t], a1 = xa[Tt + t], a2 = xa[2*Tt + t], a3 = xa[3*Tt + t];
        float zp = cz + a0*mz0 + a1*mz1 + a2*mz2 + a3*mz3;
        float hp = ch + a0*mh0 + a1*mh1 + a2*mh2 + a3*mh3;
        float Z  = 1.f / (1.f + __expf(-zp));
        float Ht = tanhf(hp);
        Hacc += g_probs[t] * (1.f - Z) * Ht;   // Hn = Z*0 + (1-Z)*Ht
    }
    float h = fmaxf(Hacc, 0.f);

    float o[HORZ];
    #pragma unroll
    for (int j = 0; j < HORZ; ++j) o[j] = h * Wout[lane*HORZ + j];
    #pragma unroll
    for (int off = 16; off; off >>= 1)
        #pragma unroll
        for (int j = 0; j < HORZ; ++j)
            o[j] += __shfl_xor_sync(0xffffffffu, o[j], off);

    if (lane == 0) {
        #pragma unroll
        for (int j = 0; j < HORZ; ++j)
            out[warp*HORZ + j] = o[j] + bout[j];
    }
}

// ---------------- launch ----------------------------------------------------
extern "C" void kernel_launch(void* const* d_in, const int* in_sizes, int n_in,
                              void* d_out, int out_size) {
    const float* x    = (const float*)d_in[0];
    const int*   ei   = (const int*)d_in[1];     // int32 (JAX x64 disabled)
    const float* ew   = (const float*)d_in[2];
    const float* att  = (const float*)d_in[3];
    const float* Wz   = (const float*)d_in[4];
    const float* bz   = (const float*)d_in[5];
    const float* Wlz  = (const float*)d_in[6];
    const float* blz  = (const float*)d_in[7];
    // d_in[8..11] = Wr, br, Wlr, blr -> dead (H0 == 0 forever)
    const float* Wh   = (const float*)d_in[12];
    const float* bh   = (const float*)d_in[13];
    const float* Wlh  = (const float*)d_in[14];
    const float* blh  = (const float*)d_in[15];
    const float* Wout = (const float*)d_in[16];
    const float* bout = (const float*)d_in[17];
    float*       out  = (float*)d_out;

    void* zp = nullptr;
    cudaGetSymbolAddress(&zp, g_zero);
    cudaMemsetAsync(zp, 0, (2*Nn + 1) * sizeof(unsigned int));

    k_hist<<<(Ee + 255) / 256, 256>>>(ei, ew, att, Wz, bz, Wlz, blz, Wh, bh, Wlh, blh);
    k_scan<<<NTILES, TILE>>>();
    k_scatter<<<(Ee + 255) / 256, 256>>>(ei, ew);
    k_aggfinal<<<(Nn * 32 + 255) / 256, 256>>>(x, Wout, bout, out);
}

// round 7
// speedup vs baseline: 1.5155x; 1.2165x over previous
#include <cuda_runtime.h>

#define Nn    50000
#define Ee    800000
#define Ff    4
#define Tt    12
#define Cc    32
#define HORZ  12
#define FT    (Ff*Tt)     // 48
#define TILE  512
#define NTILES ((Nn + TILE - 1) / TILE)   // 98

// ---------------- scratch (device globals; no allocation allowed) ----------
// zeroed each run by one cudaMemsetAsync:
//   [0, Nn)   : weighted degree (float)
//   [Nn, 2Nn) : edge count (int)
//   [2Nn]     : done-counter for last-block scan
__device__ unsigned int g_zero[2*Nn + 1];
__device__ float  g_dis[Nn];
__device__ int    g_ptrloc[Nn];       // tile-local exclusive scan of counts
__device__ int    g_cur[Nn];          // scatter cursors (tile-local)
__device__ int    g_tilesum[NTILES];
__device__ int    g_tileoff[NTILES];  // exclusive scan of tile sums
__device__ int2   g_edge[Ee];         // packed CSR payload {row, norm bits}
__device__ float  g_Mz[Ff*Cc];        // Wz @ Wlz[:C]
__device__ float  g_Mh[Ff*Cc];        // Wh @ Wlh[:C]
__device__ float  g_cz[Cc];           // bz @ Wlz[:C] + blz
__device__ float  g_ch[Cc];
__device__ float  g_probs[Tt];

static __device__ __forceinline__ float tanh_fast(float v) {
    float r;
    asm("tanh.approx.f32 %0, %1;" : "=f"(r) : "f"(v));
    return r;
}

// ---------------- histogram + (block 0) folded-weight setup ---------------
__global__ void k_hist(const int* __restrict__ ei, const float* __restrict__ ew,
                       const float* __restrict__ att,
                       const float* __restrict__ Wz, const float* __restrict__ bz,
                       const float* __restrict__ Wlz, const float* __restrict__ blz,
                       const float* __restrict__ Wh, const float* __restrict__ bh,
                       const float* __restrict__ Wlh, const float* __restrict__ blh) {
    float* deg = (float*)g_zero;
    int*   cnt = (int*)(g_zero + Nn);
    int e = blockIdx.x * blockDim.x + threadIdx.x;
    if (e < Ee) {
        int col = ei[Ee + e];
        atomicAdd(&deg[col], ew[e]);
        atomicAdd(&cnt[col], 1);
    }
    // block 0 additionally folds the weights (H0 == 0 forever -> R gate dead,
    // concat collapses: M = W @ Wl[:C], c = b @ Wl[:C] + bl)
    if (blockIdx.x == 0) {
        int tid = threadIdx.x;
        if (tid < Ff*Cc) {
            int f = tid / Cc, c = tid % Cc;
            float sz = 0.f, sh = 0.f;
            #pragma unroll
            for (int k = 0; k < Cc; ++k) {
                sz += Wz[f*Cc + k] * Wlz[k*Cc + c];
                sh += Wh[f*Cc + k] * Wlh[k*Cc + c];
            }
            g_Mz[tid] = sz;
            g_Mh[tid] = sh;
        }
        if (tid < Cc) {
            float sz = 0.f, sh = 0.f;
            #pragma unroll
            for (int k = 0; k < Cc; ++k) {
                sz += bz[k] * Wlz[k*Cc + tid];
                sh += bh[k] * Wlh[k*Cc + tid];
            }
            g_cz[tid] = sz + blz[tid];
            g_ch[tid] = sh + blh[tid];
        }
        if (tid == 0) {
            float m = -1e30f;
            for (int t = 0; t < Tt; ++t) m = fmaxf(m, att[t]);
            float ex[Tt], s = 0.f;
            for (int t = 0; t < Tt; ++t) { ex[t] = expf(att[t] - m); s += ex[t]; }
            float inv = 1.f / s;
            for (int t = 0; t < Tt; ++t) g_probs[t] = ex[t] * inv;
        }
    }
}

// ---------------- dis + per-tile scan + last-block tile-total scan ---------
__global__ void k_scan() {
    const float* deg = (const float*)g_zero;
    const int*   cnt = (const int*)(g_zero + Nn);
    __shared__ int sh[TILE];
    int t = threadIdx.x;
    int i = blockIdx.x * TILE + t;
    int v = (i < Nn) ? cnt[i] : 0;
    if (i < Nn) g_dis[i] = rsqrtf(deg[i] + 1.f);
    sh[t] = v;
    __syncthreads();
    #pragma unroll
    for (int off = 1; off < TILE; off <<= 1) {
        int add = (t >= off) ? sh[t - off] : 0;
        __syncthreads();
        sh[t] += add;
        __syncthreads();
    }
    if (i < Nn) { int p = sh[t] - v; g_ptrloc[i] = p; g_cur[i] = p; }
    if (t == TILE - 1) g_tilesum[blockIdx.x] = sh[t];

    // last-arriving block scans the 98 tile sums -> g_tileoff
    __threadfence();
    __shared__ int isLast;
    if (t == 0) {
        unsigned int old = atomicAdd(&g_zero[2*Nn], 1u);
        isLast = (old == NTILES - 1);
    }
    __syncthreads();
    if (isLast) {
        __shared__ int s2[128];
        int w = (t < NTILES) ? g_tilesum[t] : 0;
        if (t < 128) s2[t] = w;
        __syncthreads();
        #pragma unroll
        for (int off = 1; off < 128; off <<= 1) {
            int add = (t < 128 && t >= off) ? s2[t - off] : 0;
            __syncthreads();
            if (t < 128) s2[t] += add;
            __syncthreads();
        }
        if (t < NTILES) g_tileoff[t] = s2[t] - w;   // exclusive
    }
}

// ---------------- scatter edges into CSR slots (packed int2) ---------------
__global__ void k_scatter(const int* __restrict__ ei,
                          const float* __restrict__ ew) {
    int e = blockIdx.x * blockDim.x + threadIdx.x;
    if (e >= Ee) return;
    int r = ei[e];
    int c = ei[Ee + e];
    float nm = g_dis[r] * ew[e] * g_dis[c];
    int pos = atomicAdd(&g_cur[c], 1) + g_tileoff[c >> 9];
    g_edge[pos] = make_int2(r, __float_as_int(nm));
}

// ---------------- fused gather aggregation + GRU-lite epilogue -------------
// one warp per node; 2 edges processed in parallel (12 float4 lanes each)
__global__ void __launch_bounds__(256) k_aggfinal(
                           const float* __restrict__ x,
                           const float* __restrict__ Wout,
                           const float* __restrict__ bout,
                           float* __restrict__ out) {
    __shared__ float4 s_x[8][12];        // aggregated 48-vector per warp
    __shared__ float  s_h[8][32];        // per-channel h per warp
    __shared__ float  s_w[Cc * HORZ];    // Wout cached per block

    int tid  = threadIdx.x;
    for (int i = tid; i < Cc * HORZ; i += 256) s_w[i] = Wout[i];
    __syncthreads();

    int warp = (blockIdx.x << 3) + (tid >> 5);
    int wl   = tid >> 5;
    int lane = tid & 31;
    if (warp >= Nn) return;

    int beg = g_ptrloc[warp] + g_tileoff[warp >> 9];
    int end = (warp == Nn - 1) ? Ee
            : (g_ptrloc[warp + 1] + g_tileoff[(warp + 1) >> 9]);
    float d  = g_dis[warp];
    float sn = d * d;

    const float4* __restrict__ X4 = (const float4*)x;   // [n][12] float4
    int  half = (lane >= 12) ? 1 : 0;     // edge slot within pair
    int  q    = lane - 12 * half;         // float4 index 0..11
    bool act  = lane < 24;

    float4 acc = make_float4(0.f, 0.f, 0.f, 0.f);
    if (lane < 12) {                      // self-loop term (half 0 only)
        float4 v = X4[warp * 12 + lane];
        acc.x = sn * v.x; acc.y = sn * v.y; acc.z = sn * v.z; acc.w = sn * v.w;
    }

    for (int base = beg; base < end; base += 32) {
        int k = base + lane;
        int2 ed = make_int2(0, 0);
        if (k < end) ed = g_edge[k];
        int cnt = min(32, end - base);
        #pragma unroll 2
        for (int i = 0; i < cnt; i += 2) {
            int src = i + half;
            int   rr = __shfl_sync(0xffffffffu, ed.x, src);
            float nn = __int_as_float(__shfl_sync(0xffffffffu, ed.y, src));
            if (act && src < cnt) {
                float4 v = X4[rr * 12 + q];
                acc.x += nn * v.x; acc.y += nn * v.y;
                acc.z += nn * v.z; acc.w += nn * v.w;
            }
        }
    }
    // merge the two edge-slot halves: lane L += lane L+12
    acc.x += __shfl_down_sync(0xffffffffu, acc.x, 12);
    acc.y += __shfl_down_sync(0xffffffffu, acc.y, 12);
    acc.z += __shfl_down_sync(0xffffffffu, acc.z, 12);
    acc.w += __shfl_down_sync(0xffffffffu, acc.w, 12);
    if (lane < 12) s_x[wl][lane] = acc;
    __syncwarp();

    // ----- GRU-lite epilogue: lane = channel -----
    const float* xa = (const float*)s_x[wl];   // 48 floats, layout f*12 + t
    float mz0 = g_Mz[lane],        mz1 = g_Mz[Cc + lane];
    float mz2 = g_Mz[2*Cc + lane], mz3 = g_Mz[3*Cc + lane];
    float mh0 = g_Mh[lane],        mh1 = g_Mh[Cc + lane];
    float mh2 = g_Mh[2*Cc + lane], mh3 = g_Mh[3*Cc + lane];
    float cz  = g_cz[lane],        ch  = g_ch[lane];

    float Hacc = 0.f;
    #pragma unroll
    for (int t = 0; t < Tt; ++t) {
        float a0 = xa[t], a1 = xa[Tt + t], a2 = xa[2*Tt + t], a3 = xa[3*Tt + t];
        float zp = cz + a0*mz0 + a1*mz1 + a2*mz2 + a3*mz3;
        float hp = ch + a0*mh0 + a1*mh1 + a2*mh2 + a3*mh3;
        // sigmoid(zp) = 0.5 + 0.5*tanh(zp/2)  ->  (1-Z) = 0.5 - 0.5*tanh(zp/2)
        float tz = tanh_fast(0.5f * zp);
        float th = tanh_fast(hp);
        float omz = __fmaf_rn(-0.5f, tz, 0.5f);
        Hacc = __fmaf_rn(g_probs[t] * omz, th, Hacc);   // Hn = (1-Z)*Ht
    }
    float h = fmaxf(Hacc, 0.f);
    s_h[wl][lane] = h;
    __syncwarp();

    // ----- output GEMV: split channels over two half-warps -----
    int  half2 = (lane >= 16) ? 1 : 0;
    int  j     = lane - 16 * half2;      // output index 0..11 (12..15 idle)
    float o = 0.f;
    if (j < HORZ) {
        #pragma unroll
        for (int c = 0; c < Cc; c += 2) {
            int cc = c + half2;
            o += s_h[wl][cc] * s_w[cc * HORZ + j];
        }
    }
    o += __shfl_down_sync(0xffffffffu, o, 16);
    if (lane < HORZ)
        out[warp * HORZ + lane] = o + bout[lane];
}

// ---------------- launch ----------------------------------------------------
extern "C" void kernel_launch(void* const* d_in, const int* in_sizes, int n_in,
                              void* d_out, int out_size) {
    const float* x    = (const float*)d_in[0];
    const int*   ei   = (const int*)d_in[1];     // int32 (JAX x64 disabled)
    const float* ew   = (const float*)d_in[2];
    const float* att  = (const float*)d_in[3];
    const float* Wz   = (const float*)d_in[4];
    const float* bz   = (const float*)d_in[5];
    const float* Wlz  = (const float*)d_in[6];
    const float* blz  = (const float*)d_in[7];
    // d_in[8..11] = Wr, br, Wlr, blr -> dead (H0 == 0 forever)
    const float* Wh   = (const float*)d_in[12];
    const float* bh   = (const float*)d_in[13];
    const float* Wlh  = (const float*)d_in[14];
    const float* blh  = (const float*)d_in[15];
    const float* Wout = (const float*)d_in[16];
    const float* bout = (const float*)d_in[17];
    float*       out  = (float*)d_out;

    void* zp = nullptr;
    cudaGetSymbolAddress(&zp, g_zero);
    cudaMemsetAsync(zp, 0, (2*Nn + 1) * sizeof(unsigned int));

    k_hist<<<(Ee + 255) / 256, 256>>>(ei, ew, att, Wz, bz, Wlz, blz, Wh, bh, Wlh, blh);
    k_scan<<<NTILES, TILE>>>();
    k_scatter<<<(Ee + 255) / 256, 256>>>(ei, ew);
    k_aggfinal<<<(Nn * 32 + 255) / 256, 256>>>(x, Wout, bout, out);
}